// round 14
// baseline (speedup 1.0000x reference)
#include <cuda_runtime.h>
#include <cstddef>
#include <cstdint>

#define NIMG 8192
#define ACT_STRIDE 8256            /* >= 147*56 = 8232; 16B-aligned rows */
#define GFC 56
#define NBLK_FC 147
#define NBLK_CONV 148

// Transposed activations: g_actT[k][img], k in [0,400). Tail stays zero (.bss).
__device__ __align__(16) float g_actT[(size_t)400 * ACT_STRIDE];
// Pre-transposed fc weights (filled by conv blocks 0..31)
__device__ __align__(16) float g_w1T[400 * 120];
__device__ __align__(16) float g_w2T[120 * 84];

__device__ __forceinline__ void cp16(uint32_t dst, const void* src) {
    asm volatile("cp.async.cg.shared.global [%0], [%1], 16;" :: "r"(dst), "l"(src));
}
#define CP_COMMIT() asm volatile("cp.async.commit_group;")
#define CP_WAIT0()  asm volatile("cp.async.wait_group 0;")
#define CP_WAIT1()  asm volatile("cp.async.wait_group 1;")

// ---------------------------------------------------------------------------
// Kernel 1: PERSISTENT fused conv1->relu->pool1->conv2->relu->pool2.
// 148 blocks x 256 threads (8 warps), warp-per-image, groups of 8 images.
// Blocks 0..135 run 7 groups, 136..147 run 6 (exactly 8192 images).
// Patches double-buffered: group g+1 streams in via cp.async during group g.
// ---------------------------------------------------------------------------
__global__ __launch_bounds__(256) void conv_kernel(const float* __restrict__ x,
                                                   const float* __restrict__ w1,
                                                   const float* __restrict__ w2,
                                                   const float* __restrict__ fw1,
                                                   const float* __restrict__ fw2)
{
    extern __shared__ __align__(16) float cm[];
    float* s_P   = cm;                  // 2 x [8][768] = 12288 (patch dbl-buf)
    float* s_c1  = s_P + 12288;         // [8][880]  c1 (864) then c2 (768)
    float* s_p1  = s_c1 + 8 * 880;      // [8][768]  p1 (720)
    float* s_out = s_p1 + 8 * 768;      // [400][8]  = 3200
    float* s_w1  = s_out + 3200;        // 456
    float* s_w2  = s_w1 + 456;          // 2400

    const int tid  = threadIdx.x;
    const int wid  = tid >> 5;
    const int lane = tid & 31;
    const int b    = blockIdx.x;

    const int start   = (b < 136) ? b * 56 : 7616 + (b - 136) * 48;
    const int ngroups = (b < 136) ? 7 : 6;

    const uint32_t p_base = (uint32_t)__cvta_generic_to_shared(s_P);

    // async patch prefetch for group gg into buffer gg&1
    auto prefetch = [&](int gg) {
        const int buf = (gg & 1) * 6144;
        const int ib  = start + gg * 8;
        #pragma unroll
        for (int i = 0; i < 6; i++) {
            int j = tid + i * 256;           // 1536 cp16 total
            int w = j / 192;
            int r = j % 192;
            int c = r >> 6;
            int rr = (r & 63) >> 2;
            int sg = (r & 3) * 4;
            cp16(p_base + (uint32_t)(buf + w * 768 + c * 256 + rr * 16 + sg) * 4,
                 &x[(size_t)(ib + w) * 3072 + c * 1024 + rr * 32 + sg]);
        }
    };

    prefetch(0); CP_COMMIT();

    // weights (plain loads, overlap with group-0 prefetch)
    for (int i = tid; i < 450; i += 256) s_w1[i] = w1[i];
    for (int i = tid; i < 2400; i += 256) s_w2[i] = w2[i];

    // side-job: fc weight transposes (blocks 0..31, overlaps prefetch)
    if (b < 32) {
        for (int j = tid; j < 1500; j += 256) {
            int idx = b * 1500 + j;
            int o = idx % 120, k = idx / 120;
            g_w1T[k * 120 + o] = fw1[o * 400 + k];
        }
        for (int j = tid; j < 315; j += 256) {
            int idx = b * 315 + j;
            int o = idx % 84, k = idx / 84;
            g_w2T[k * 84 + o] = fw2[o * 120 + k];
        }
    }

    CP_WAIT0();
    __syncthreads();

    float* C1 = &s_c1[wid * 880];
    float* P1 = &s_p1[wid * 768];

    for (int g = 0; g < ngroups; g++) {
        if (g + 1 < ngroups) { prefetch(g + 1); CP_COMMIT(); }

        const float* A = &s_P[(g & 1) * 6144 + wid * 768];

        // ---- conv1 + relu: 96 tasks, each 3x3 outputs; sliding-row form
        #pragma unroll
        for (int pass = 0; pass < 3; pass++) {
            int u   = lane + pass * 32;
            int oc  = u >> 4;
            int rem = u & 15;
            int r0  = (rem >> 2) * 3;
            int c0  = (rem & 3) * 3;
            float acc[3][3];
            #pragma unroll
            for (int i = 0; i < 3; i++)
                #pragma unroll
                for (int j = 0; j < 3; j++) acc[i][j] = 0.f;

            for (int c = 0; c < 3; c++) {
                float wreg[25];
                const float* wb = &s_w1[(oc * 3 + c) * 25];
                #pragma unroll
                for (int i = 0; i < 25; i++) wreg[i] = wb[i];
                const float* Ac = &A[c * 256];
                #pragma unroll
                for (int rr = 0; rr < 7; rr++) {
                    float p[7];
                    const float* pr = &Ac[(r0 + rr) * 16 + c0];
                    #pragma unroll
                    for (int j = 0; j < 7; j++) p[j] = pr[j];
                    #pragma unroll
                    for (int orow = 0; orow < 3; orow++) {
                        int uu = rr - orow;
                        if (uu >= 0 && uu < 5) {
                            #pragma unroll
                            for (int v = 0; v < 5; v++) {
                                float w = wreg[uu * 5 + v];
                                #pragma unroll
                                for (int j = 0; j < 3; j++)
                                    acc[orow][j] += p[v + j] * w;
                            }
                        }
                    }
                }
            }
            #pragma unroll
            for (int orow = 0; orow < 3; orow++)
                #pragma unroll
                for (int j = 0; j < 3; j++)
                    C1[(oc * 12 + r0 + orow) * 12 + c0 + j] = fmaxf(acc[orow][j], 0.f);
        }
        __syncwarp();

        // ---- pool1 (stride-1 2x2, top-left 10x10) -> P1[6][10][12]
        for (int t = lane; t < 600; t += 32) {
            int oc = t / 100;
            int rr = (t % 100) / 10;
            int cc = t % 10;
            const float* c1 = &C1[(oc * 12 + rr) * 12 + cc];
            P1[(oc * 10 + rr) * 12 + cc] =
                fmaxf(fmaxf(c1[0], c1[1]), fmaxf(c1[12], c1[13]));
        }
        __syncwarp();

        // ---- conv2 + relu: 32 tasks = oc(16) x rowhalf(2) -> C1 as c2[16][6][8]
        {
            int oc = lane >> 1;
            int r0 = (lane & 1) * 3;
            float acc[3][6];
            #pragma unroll
            for (int i = 0; i < 3; i++)
                #pragma unroll
                for (int j = 0; j < 6; j++) acc[i][j] = 0.f;

            for (int c = 0; c < 6; c++) {
                float wreg[25];
                const float* wb = &s_w2[(oc * 6 + c) * 25];
                #pragma unroll
                for (int i = 0; i < 25; i++) wreg[i] = wb[i];
                #pragma unroll
                for (int rr = 0; rr < 7; rr++) {
                    const float* pr = &P1[(c * 10 + r0 + rr) * 12];
                    float p[10];
                    float4 v0 = *reinterpret_cast<const float4*>(&pr[0]);
                    float4 v1 = *reinterpret_cast<const float4*>(&pr[4]);
                    p[0] = v0.x; p[1] = v0.y; p[2] = v0.z; p[3] = v0.w;
                    p[4] = v1.x; p[5] = v1.y; p[6] = v1.z; p[7] = v1.w;
                    p[8] = pr[8]; p[9] = pr[9];
                    #pragma unroll
                    for (int orow = 0; orow < 3; orow++) {
                        int uu = rr - orow;
                        if (uu >= 0 && uu < 5) {
                            #pragma unroll
                            for (int v = 0; v < 5; v++) {
                                float w = wreg[uu * 5 + v];
                                #pragma unroll
                                for (int j = 0; j < 6; j++)
                                    acc[orow][j] += p[v + j] * w;
                            }
                        }
                    }
                }
            }
            #pragma unroll
            for (int orow = 0; orow < 3; orow++)
                #pragma unroll
                for (int j = 0; j < 6; j++)
                    C1[(oc * 6 + r0 + orow) * 8 + j] = fmaxf(acc[orow][j], 0.f);
        }
        __syncwarp();

        // ---- pool2 -> s_out[k][8]
        for (int t = lane; t < 400; t += 32) {
            int oc = t / 25;
            int rr = (t % 25) / 5;
            int cc = t % 5;
            const float* c2 = &C1[(oc * 6 + rr) * 8 + cc];
            s_out[t * 8 + wid] = fmaxf(fmaxf(c2[0], c2[1]), fmaxf(c2[8], c2[9]));
        }
        __syncthreads();

        // ---- coalesced transposed store (img0 multiple of 8 -> 32B aligned)
        const int img0 = start + g * 8;
        for (int k = tid; k < 400; k += 256) {
            float4 v0 = *reinterpret_cast<const float4*>(&s_out[k * 8]);
            float4 v1 = *reinterpret_cast<const float4*>(&s_out[k * 8 + 4]);
            float* dst = &g_actT[(size_t)k * ACT_STRIDE + img0];
            *reinterpret_cast<float4*>(dst)     = v0;
            *reinterpret_cast<float4*>(dst + 4) = v1;
        }

        CP_WAIT0();        // next group's patches landed
        __syncthreads();   // s_out store done; safe to overwrite next group
    }
}

// ---------------------------------------------------------------------------
// Kernel 2: fused fc1(relu) -> fc2(relu) -> fc3 (R13, unchanged).
// 147 blocks x 512 threads; K-split by 2; cp.async-staged chunks of 80.
// ---------------------------------------------------------------------------
#define WCH 80
#define NCH 5
#define AROW 56
#define WROW 124
#define STGF (WCH * AROW + WCH * WROW)   /* 14400 floats per stage */

__global__ __launch_bounds__(512) void fc_kernel(const float* __restrict__ fb1,
                                                 const float* __restrict__ fb2,
                                                 const float* __restrict__ fw3,
                                                 const float* __restrict__ fb3,
                                                 float* __restrict__ out)
{
    extern __shared__ __align__(16) float sm[];
    float* s_stg  = sm;                      // 2 x 14400 = 28800
    float* s_h1T  = sm + 2 * STGF;           // [120][56] = 6720
    float* s_w2T  = s_h1T + 120 * GFC;       // [120][84] = 10080
    float* s_w3   = s_w2T + 120 * 84;        // 840
    float* s_b1   = s_w3 + 840;              // 120
    float* s_b2   = s_b1 + 120;              // 84
    float* s_b3   = s_b2 + 84;               // 12 (pad)
    float* s_h2   = sm;                      // alias after fc1: [56][84]

    const int tid  = threadIdx.x;
    const int img0 = blockIdx.x * GFC;
    const int g    = tid >> 8;
    const int sub  = tid & 255;

    const uint32_t s_base = (uint32_t)__cvta_generic_to_shared(sm);

    auto stage = [&](int ch) {
        const int buf = (ch & 1) * STGF;
        const size_t kc = (size_t)ch * WCH;
        for (int j = tid; j < 3520; j += 512) {
            if (j < 1120) {
                int row = j / 14, seg = (j % 14) * 4;
                cp16(s_base + (uint32_t)(buf + row * AROW + seg) * 4,
                     &g_actT[(kc + row) * ACT_STRIDE + img0 + seg]);
            } else {
                int q = j - 1120;
                int row = q / 30, seg = (q % 30) * 4;
                cp16(s_base + (uint32_t)(buf + WCH * AROW + row * WROW + seg) * 4,
                     &g_w1T[(kc + row) * 120 + seg]);
            }
        }
    };

    stage(0); CP_COMMIT();
    stage(1);
    for (int j = tid; j < 2520; j += 512)
        cp16(s_base + (uint32_t)(2 * STGF + 6720 + j * 4) * 4, &g_w2T[j * 4]);
    CP_COMMIT();
    for (int i = tid; i < 840; i += 512) s_w3[i] = fw3[i];
    if (tid < 120) s_b1[tid] = fb1[tid];
    else if (tid < 204) s_b2[tid - 120] = fb2[tid - 120];
    else if (tid < 214) s_b3[tid - 204] = fb3[tid - 204];
    CP_WAIT1();
    __syncthreads();

    const int o0 = (sub % 30) * 4;
    const int i0 = (sub / 30) * 8;
    const bool active = (sub < 210);
    const int kofs = g * (WCH / 2);
    float acc[8][4];
    #pragma unroll
    for (int i = 0; i < 8; i++)
        #pragma unroll
        for (int j = 0; j < 4; j++) acc[i][j] = 0.f;

    for (int ch = 0; ch < NCH; ch++) {
        const float* abuf = s_stg + (ch & 1) * STGF + kofs * AROW;
        const float* wbuf = s_stg + (ch & 1) * STGF + WCH * AROW + kofs * WROW;
        if (active) {
            #pragma unroll 5
            for (int kk = 0; kk < WCH / 2; kk++) {
                float4 w  = *reinterpret_cast<const float4*>(&wbuf[kk * WROW + o0]);
                float4 a0 = *reinterpret_cast<const float4*>(&abuf[kk * AROW + i0]);
                float4 a1 = *reinterpret_cast<const float4*>(&abuf[kk * AROW + i0 + 4]);
                acc[0][0] += a0.x * w.x; acc[0][1] += a0.x * w.y; acc[0][2] += a0.x * w.z; acc[0][3] += a0.x * w.w;
                acc[1][0] += a0.y * w.x; acc[1][1] += a0.y * w.y; acc[1][2] += a0.y * w.z; acc[1][3] += a0.y * w.w;
                acc[2][0] += a0.z * w.x; acc[2][1] += a0.z * w.y; acc[2][2] += a0.z * w.z; acc[2][3] += a0.z * w.w;
                acc[3][0] += a0.w * w.x; acc[3][1] += a0.w * w.y; acc[3][2] += a0.w * w.z; acc[3][3] += a0.w * w.w;
                acc[4][0] += a1.x * w.x; acc[4][1] += a1.x * w.y; acc[4][2] += a1.x * w.z; acc[4][3] += a1.x * w.w;
                acc[5][0] += a1.y * w.x; acc[5][1] += a1.y * w.y; acc[5][2] += a1.y * w.z; acc[5][3] += a1.y * w.w;
                acc[6][0] += a1.z * w.x; acc[6][1] += a1.z * w.y; acc[6][2] += a1.z * w.z; acc[6][3] += a1.z * w.w;
                acc[7][0] += a1.w * w.x; acc[7][1] += a1.w * w.y; acc[7][2] += a1.w * w.z; acc[7][3] += a1.w * w.w;
            }
        }
        __syncthreads();
        if (ch + 2 < NCH) stage(ch + 2);
        CP_COMMIT();
        CP_WAIT1();
        __syncthreads();
    }

    if (g == 0 && active) {
        #pragma unroll
        for (int oo = 0; oo < 4; oo++)
            #pragma unroll
            for (int ii = 0; ii < 8; ii++)
                s_h1T[(o0 + oo) * GFC + i0 + ii] = acc[ii][oo];
    }
    __syncthreads();
    if (g == 1 && active) {
        #pragma unroll
        for (int oo = 0; oo < 4; oo++) {
            float b = s_b1[o0 + oo];
            #pragma unroll
            for (int ii = 0; ii < 8; ii++) {
                float* p = &s_h1T[(o0 + oo) * GFC + i0 + ii];
                *p = fmaxf(*p + acc[ii][oo] + b, 0.f);
            }
        }
    }
    __syncthreads();

    {
        const bool act2 = (sub < 147);
        int oo0 = (sub % 21) * 4;
        int ii0 = (sub / 21) * 8;
        float c2[8][4];
        #pragma unroll
        for (int i = 0; i < 8; i++)
            #pragma unroll
            for (int j = 0; j < 4; j++) c2[i][j] = 0.f;
        if (act2) {
            const int k0 = g * 60;
            #pragma unroll 6
            for (int kk = 0; kk < 60; kk++) {
                int k = k0 + kk;
                float4 w  = *reinterpret_cast<const float4*>(&s_w2T[k * 84 + oo0]);
                float4 a0 = *reinterpret_cast<const float4*>(&s_h1T[k * GFC + ii0]);
                float4 a1 = *reinterpret_cast<const float4*>(&s_h1T[k * GFC + ii0 + 4]);
                c2[0][0] += a0.x * w.x; c2[0][1] += a0.x * w.y; c2[0][2] += a0.x * w.z; c2[0][3] += a0.x * w.w;
                c2[1][0] += a0.y * w.x; c2[1][1] += a0.y * w.y; c2[1][2] += a0.y * w.z; c2[1][3] += a0.y * w.w;
                c2[2][0] += a0.z * w.x; c2[2][1] += a0.z * w.y; c2[2][2] += a0.z * w.z; c2[2][3] += a0.z * w.w;
                c2[3][0] += a0.w * w.x; c2[3][1] += a0.w * w.y; c2[3][2] += a0.w * w.z; c2[3][3] += a0.w * w.w;
                c2[4][0] += a1.x * w.x; c2[4][1] += a1.x * w.y; c2[4][2] += a1.x * w.z; c2[4][3] += a1.x * w.w;
                c2[5][0] += a1.y * w.x; c2[5][1] += a1.y * w.y; c2[5][2] += a1.y * w.z; c2[5][3] += a1.y * w.w;
                c2[6][0] += a1.z * w.x; c2[6][1] += a1.z * w.y; c2[6][2] += a1.z * w.z; c2[6][3] += a1.z * w.w;
                c2[7][0] += a1.w * w.x; c2[7][1] += a1.w * w.y; c2[7][2] += a1.w * w.z; c2[7][3] += a1.w * w.w;
            }
        }
        __syncthreads();
        if (g == 0 && act2) {
            #pragma unroll
            for (int ii = 0; ii < 8; ii++)
                #pragma unroll
                for (int oo = 0; oo < 4; oo++)
                    s_h2[(ii0 + ii) * 84 + oo0 + oo] = c2[ii][oo];
        }
        __syncthreads();
        if (g == 1 && act2) {
            #pragma unroll
            for (int ii = 0; ii < 8; ii++)
                #pragma unroll
                for (int oo = 0; oo < 4; oo++) {
                    float* p = &s_h2[(ii0 + ii) * 84 + oo0 + oo];
                    *p = fmaxf(*p + c2[ii][oo] + s_b2[oo0 + oo], 0.f);
                }
        }
    }
    __syncthreads();

    for (int t = tid; t < GFC * 10; t += 512) {
        int o  = t % 10;
        int im = t / 10;
        float a = s_b3[o];
        #pragma unroll
        for (int k = 0; k < 84; k += 4) {
            float4 h = *reinterpret_cast<const float4*>(&s_h2[im * 84 + k]);
            float4 w = *reinterpret_cast<const float4*>(&s_w3[o * 84 + k]);
            a += h.x * w.x + h.y * w.y + h.z * w.z + h.w * w.w;
        }
        int gimg = img0 + im;
        if (gimg < NIMG) out[gimg * 10 + o] = a;
    }
}

extern "C" void kernel_launch(void* const* d_in, const int* in_sizes, int n_in,
                              void* d_out, int out_size)
{
    const float* x   = (const float*)d_in[0];
    const float* w1  = (const float*)d_in[1];
    const float* w2  = (const float*)d_in[2];
    const float* fw1 = (const float*)d_in[3];
    const float* fb1 = (const float*)d_in[4];
    const float* fw2 = (const float*)d_in[5];
    const float* fb2 = (const float*)d_in[6];
    const float* fw3 = (const float*)d_in[7];
    const float* fb3 = (const float*)d_in[8];
    float* out = (float*)d_out;

    const int CONV_SMEM = (12288 + 8 * 880 + 8 * 768 + 3200 + 456 + 2400) *
                          (int)sizeof(float);
    const int FC_SMEM = (2 * STGF + 120 * GFC + 120 * 84 + 840 + 120 + 84 + 12) *
                        (int)sizeof(float);
    cudaFuncSetAttribute(conv_kernel, cudaFuncAttributeMaxDynamicSharedMemorySize,
                         CONV_SMEM);
    cudaFuncSetAttribute(fc_kernel, cudaFuncAttributeMaxDynamicSharedMemorySize,
                         FC_SMEM);

    conv_kernel<<<NBLK_CONV, 256, CONV_SMEM>>>(x, w1, w2, fw1, fw2);
    fc_kernel<<<NBLK_FC, 512, FC_SMEM>>>(fb1, fb2, fw3, fb3, out);
}